// round 2
// baseline (speedup 1.0000x reference)
#include <cuda_runtime.h>
#include <cuda_bf16.h>

#define NUSERS 100000
#define NITEMS 50000
#define NNODES 150000
#define DIM 64

// ---------------- scratch (device globals: allocation-free) ----------------
__device__ float g_A[NNODES * DIM];    // layer buffer A
__device__ float g_B[NNODES * DIM];    // layer buffer B
__device__ float g_acc[NNODES * DIM];  // running accumulator (e0 + e1)
__device__ int   g_is64;               // edge_index dtype flag

// ---------------- init: concat users/items -> A, acc = A, B = 0 ------------
__global__ void k_init(const float* __restrict__ users,
                       const float* __restrict__ items,
                       const long long* __restrict__ ei_probe)
{
    if (blockIdx.x == 0 && threadIdx.x == 0) {
        // int64 vs int32 autodetect: genuine int64 indices are all < NNODES;
        // int32 data misread as int64 packs two values -> huge words.
        int is64 = 1;
        for (int i = 0; i < 64; i++) {
            long long v = ei_probe[i];
            if (v < 0 || v >= (long long)NNODES) { is64 = 0; break; }
        }
        g_is64 = is64;
    }
    const int total4 = NNODES * DIM / 4;
    const int u4n = NUSERS * DIM / 4;
    float4* A4 = reinterpret_cast<float4*>(g_A);
    float4* B4 = reinterpret_cast<float4*>(g_B);
    float4* c4 = reinterpret_cast<float4*>(g_acc);
    const float4* uu = reinterpret_cast<const float4*>(users);
    const float4* ii = reinterpret_cast<const float4*>(items);
    for (int i = blockIdx.x * blockDim.x + threadIdx.x; i < total4;
         i += gridDim.x * blockDim.x) {
        float4 v = (i < u4n) ? uu[i] : ii[i - u4n];
        A4[i] = v;
        c4[i] = v;
        B4[i] = make_float4(0.f, 0.f, 0.f, 0.f);
    }
}

// ---------------- edge scatter: dst += w * src_emb (16 threads / edge) -----
__global__ void k_scatter(const void* __restrict__ ei_raw,
                          const float* __restrict__ w,
                          int E, int src_is_A)
{
    int tid = blockIdx.x * blockDim.x + threadIdx.x;
    int e = tid >> 4;
    if (e >= E) return;
    int c = (tid & 15) << 2;  // float offset within the 64-wide row

    int s, d;
    if (g_is64) {
        const long long* ei = reinterpret_cast<const long long*>(ei_raw);
        s = (int)ei[e];
        d = (int)ei[E + e];
    } else {
        const int* ei = reinterpret_cast<const int*>(ei_raw);
        s = ei[e];
        d = ei[E + e];
    }
    float wt = __ldg(w + e);

    const float* srcE = src_is_A ? g_A : g_B;
    float*       dstE = src_is_A ? g_B : g_A;

    float4 v = *reinterpret_cast<const float4*>(srcE + s * DIM + c);
    float4 m = make_float4(v.x * wt, v.y * wt, v.z * wt, v.w * wt);
    float* p = dstE + d * DIM + c;
    asm volatile("red.global.add.v4.f32 [%0], {%1,%2,%3,%4};"
                 :: "l"(p), "f"(m.x), "f"(m.y), "f"(m.z), "f"(m.w)
                 : "memory");
}

// -------- post layer 1: B = relu(B); acc += B; A = 0 (next scatter target) -
__global__ void k_post1()
{
    const int total4 = NNODES * DIM / 4;
    float4* B4 = reinterpret_cast<float4*>(g_B);
    float4* A4 = reinterpret_cast<float4*>(g_A);
    float4* c4 = reinterpret_cast<float4*>(g_acc);
    for (int i = blockIdx.x * blockDim.x + threadIdx.x; i < total4;
         i += gridDim.x * blockDim.x) {
        float4 v = B4[i];
        v.x = fmaxf(v.x, 0.f); v.y = fmaxf(v.y, 0.f);
        v.z = fmaxf(v.z, 0.f); v.w = fmaxf(v.w, 0.f);
        B4[i] = v;  // relu'd: next layer gathers from B
        float4 a = c4[i];
        a.x += v.x; a.y += v.y; a.z += v.z; a.w += v.w;
        c4[i] = a;
        A4[i] = make_float4(0.f, 0.f, 0.f, 0.f);
    }
}

// -------- final: a = (acc + relu(A)) / 3; out = a @ W^T + b; + copies ------
__global__ void __launch_bounds__(256)
k_final(const float* __restrict__ W, const float* __restrict__ b,
        const float* __restrict__ users, const float* __restrict__ items,
        float* __restrict__ out)
{
    __shared__ float Wt[DIM][DIM + 1];  // W transposed, padded (bank-safe)
    __shared__ float sb[DIM];
    __shared__ float aSh[4][DIM];

    const int t = threadIdx.x;
    for (int idx = t; idx < DIM * DIM; idx += 256) {
        int j = idx >> 6, k = idx & 63;
        Wt[k][j] = W[idx];
    }
    if (t < DIM) sb[t] = b[t];

    const int r = t >> 6;        // row within block (0..3)
    const int j = t & 63;        // output column
    const int row = blockIdx.x * 4 + r;

    float aval = 0.f;
    if (row < NNODES) {
        int i = row * DIM + j;
        aval = (g_acc[i] + fmaxf(g_A[i], 0.f)) * (1.0f / 3.0f);
    }
    aSh[r][j] = aval;
    __syncthreads();
    if (row >= NNODES) return;

    float s = sb[j];
#pragma unroll
    for (int k = 0; k < DIM; k++) s = fmaf(aSh[r][k], Wt[k][j], s);

    if (row < NUSERS) {
        out[row * DIM + j] = s;                                   // users_final
        out[NUSERS * DIM + row * DIM + j] = users[row * DIM + j]; // users copy
    } else {
        int rr = row - NUSERS;
        out[2 * NUSERS * DIM + rr * DIM + j] = s;                 // items_final
        out[2 * NUSERS * DIM + NITEMS * DIM + rr * DIM + j] =
            items[rr * DIM + j];                                  // items copy
    }
}

// ---------------------------------------------------------------------------
extern "C" void kernel_launch(void* const* d_in, const int* in_sizes, int n_in,
                              void* d_out, int out_size)
{
    const void*  ei    = d_in[0];
    const float* w     = (const float*)d_in[1];
    const float* users = (const float*)d_in[2];
    const float* items = (const float*)d_in[3];
    const float* W     = (const float*)d_in[4];
    const float* b     = (const float*)d_in[5];
    float* out = (float*)d_out;

    const int E = in_sizes[1];  // edge_weight element count

    k_init<<<2048, 256>>>(users, items, (const long long*)ei);

    int sblocks = (E * 16 + 255) / 256;
    k_scatter<<<sblocks, 256>>>(ei, w, E, /*src_is_A=*/1);  // A -> B
    k_post1<<<2048, 256>>>();
    k_scatter<<<sblocks, 256>>>(ei, w, E, /*src_is_A=*/0);  // B -> A (raw sums)

    k_final<<<(NNODES + 3) / 4, 256>>>(W, b, users, items, out);
}

// round 6
// speedup vs baseline: 1.1050x; 1.1050x over previous
#include <cuda_runtime.h>
#include <cuda_bf16.h>

#define NUSERS 100000
#define NITEMS 50000
#define NNODES 150000
#define DIM 64

// ---------------- scratch (device globals: allocation-free) ----------------
__device__ float g_A[NNODES * DIM];    // layer-2 accumulation target
__device__ float g_B[NNODES * DIM];    // layer-1 accumulation target
__device__ int   g_is64;               // edge_index dtype flag

// ---------------- zero both buffers + dtype probe --------------------------
__global__ void k_zero(const long long* __restrict__ ei_probe)
{
    if (blockIdx.x == 0 && threadIdx.x == 0) {
        // int64 vs int32 autodetect: genuine int64 indices are all in [0, N);
        // int32 data misread as int64 packs two values -> out-of-range words.
        int is64 = 1;
        for (int i = 0; i < 64; i++) {
            long long v = ei_probe[i];
            if (v < 0 || v >= (long long)NNODES) { is64 = 0; break; }
        }
        g_is64 = is64;
    }
    const int total4 = NNODES * DIM / 4;
    float4* A4 = reinterpret_cast<float4*>(g_A);
    float4* B4 = reinterpret_cast<float4*>(g_B);
    const float4 z = make_float4(0.f, 0.f, 0.f, 0.f);
    for (int i = blockIdx.x * blockDim.x + threadIdx.x; i < total4;
         i += gridDim.x * blockDim.x) {
        A4[i] = z;
        B4[i] = z;
    }
}

// ---------------- edge scatter: dst += w * f(src_emb), 16 threads/edge -----
// layer 0: gather from users/items inputs (virtual concat), RED into B
// layer 1: gather relu(B), RED into A
__global__ void k_scatter(const void* __restrict__ ei_raw,
                          const float* __restrict__ w,
                          const float* __restrict__ users,
                          const float* __restrict__ items,
                          int E, int layer)
{
    int tid = blockIdx.x * blockDim.x + threadIdx.x;
    int e = tid >> 4;
    if (e >= E) return;
    int c = (tid & 15) << 2;  // float offset within the 64-wide row

    int s, d;
    if (g_is64) {
        const long long* ei = reinterpret_cast<const long long*>(ei_raw);
        s = (int)ei[e];
        d = (int)ei[E + e];
    } else {
        const int* ei = reinterpret_cast<const int*>(ei_raw);
        s = ei[e];
        d = ei[E + e];
    }
    float wt = __ldg(w + e);

    float4 v;
    float* dstE;
    if (layer == 0) {
        const float* src = (s < NUSERS) ? (users + s * DIM)
                                        : (items + (s - NUSERS) * DIM);
        v = *reinterpret_cast<const float4*>(src + c);
        dstE = g_B;
    } else {
        v = *reinterpret_cast<const float4*>(g_B + s * DIM + c);
        v.x = fmaxf(v.x, 0.f); v.y = fmaxf(v.y, 0.f);
        v.z = fmaxf(v.z, 0.f); v.w = fmaxf(v.w, 0.f);
        dstE = g_A;
    }

    float4 m = make_float4(v.x * wt, v.y * wt, v.z * wt, v.w * wt);
    float* p = dstE + d * DIM + c;
    asm volatile("red.global.add.v4.f32 [%0], {%1,%2,%3,%4};"
                 :: "l"(p), "f"(m.x), "f"(m.y), "f"(m.z), "f"(m.w)
                 : "memory");
}

// -------- final: a = (orig + relu(B) + relu(A)) / 3; out = a@W^T + b -------
// Persistent grid-stride: W staged in SMEM once per block.
__global__ void __launch_bounds__(256)
k_final(const float* __restrict__ W, const float* __restrict__ b,
        const float* __restrict__ users, const float* __restrict__ items,
        float* __restrict__ out)
{
    __shared__ float Wt[DIM][DIM + 1];  // W transposed, padded (bank-safe)
    __shared__ float sb[DIM];
    __shared__ float aSh[4][DIM];

    const int t = threadIdx.x;
    for (int idx = t; idx < DIM * DIM; idx += 256) {
        int j = idx >> 6, k = idx & 63;
        Wt[k][j] = W[idx];
    }
    if (t < DIM) sb[t] = b[t];

    const int r = t >> 6;   // row-slot within block (0..3)
    const int j = t & 63;   // column

    for (int base = blockIdx.x * 4; base < NNODES; base += gridDim.x * 4) {
        const int row = base + r;
        float aval = 0.f, orig = 0.f;
        if (row < NNODES) {
            int i = row * DIM + j;
            orig = (row < NUSERS) ? users[i]
                                  : items[(row - NUSERS) * DIM + j];
            aval = (orig + fmaxf(g_B[i], 0.f) + fmaxf(g_A[i], 0.f))
                   * (1.0f / 3.0f);
        }
        __syncthreads();        // previous iteration's aSh readers done
        aSh[r][j] = aval;
        __syncthreads();

        if (row < NNODES) {
            float s = sb[j];
#pragma unroll
            for (int k = 0; k < DIM; k++) s = fmaf(aSh[r][k], Wt[k][j], s);

            if (row < NUSERS) {
                out[row * DIM + j] = s;                       // users_final
                out[NUSERS * DIM + row * DIM + j] = orig;     // users copy
            } else {
                int rr = row - NUSERS;
                out[2 * NUSERS * DIM + rr * DIM + j] = s;     // items_final
                out[2 * NUSERS * DIM + NITEMS * DIM + rr * DIM + j] = orig;
            }
        }
    }
}

// ---------------------------------------------------------------------------
extern "C" void kernel_launch(void* const* d_in, const int* in_sizes, int n_in,
                              void* d_out, int out_size)
{
    const void*  ei    = d_in[0];
    const float* w     = (const float*)d_in[1];
    const float* users = (const float*)d_in[2];
    const float* items = (const float*)d_in[3];
    const float* W     = (const float*)d_in[4];
    const float* b     = (const float*)d_in[5];
    float* out = (float*)d_out;

    const int E = in_sizes[1];  // edge_weight element count

    k_zero<<<2048, 256>>>((const long long*)ei);

    int sblocks = (E * 16 + 255) / 256;
    k_scatter<<<sblocks, 256>>>(ei, w, users, items, E, 0);  // inputs -> B
    k_scatter<<<sblocks, 256>>>(ei, w, users, items, E, 1);  // relu(B) -> A

    k_final<<<1480, 256>>>(W, b, users, items, out);
}

// round 7
// speedup vs baseline: 1.6183x; 1.4645x over previous
#include <cuda_runtime.h>
#include <cuda_bf16.h>

#define NUSERS 100000
#define NITEMS 50000
#define NNODES 150000
#define DIM 64

// ---------------- scratch (device globals: allocation-free) ----------------
__device__ float g_A[NNODES * DIM];    // layer-2 accumulation target
__device__ float g_B[NNODES * DIM];    // layer-1 accumulation target
__device__ int   g_is64;               // edge_index dtype flag

// ---------------- zero both buffers + dtype probe --------------------------
__global__ void k_zero(const long long* __restrict__ ei_probe)
{
    if (blockIdx.x == 0 && threadIdx.x == 0) {
        int is64 = 1;
        for (int i = 0; i < 64; i++) {
            long long v = ei_probe[i];
            if (v < 0 || v >= (long long)NNODES) { is64 = 0; break; }
        }
        g_is64 = is64;
    }
    const int total4 = NNODES * DIM / 4;
    float4* A4 = reinterpret_cast<float4*>(g_A);
    float4* B4 = reinterpret_cast<float4*>(g_B);
    const float4 z = make_float4(0.f, 0.f, 0.f, 0.f);
    for (int i = blockIdx.x * blockDim.x + threadIdx.x; i < total4;
         i += gridDim.x * blockDim.x) {
        A4[i] = z;
        B4[i] = z;
    }
}

// ------------- edge scatter: 2 edges / thread, 16 threads / edge -----------
// layer 0: gather users/items (virtual concat) -> RED into B
// layer 1: gather relu(B) -> RED into A
__global__ void k_scatter(const void* __restrict__ ei_raw,
                          const float* __restrict__ w,
                          const float* __restrict__ users,
                          const float* __restrict__ items,
                          int E, int Eh, int layer)
{
    int tid = blockIdx.x * blockDim.x + threadIdx.x;
    int eh = tid >> 4;
    if (eh >= Eh) return;
    const int c = (tid & 15) << 2;     // float offset within 64-wide row

    const int e0 = eh;
    const int e1 = eh + Eh;
    const bool has2 = (e1 < E);

    int s0, d0, s1 = 0, d1 = 0;
    if (g_is64) {
        const long long* ei = reinterpret_cast<const long long*>(ei_raw);
        s0 = (int)ei[e0];  d0 = (int)ei[E + e0];
        if (has2) { s1 = (int)ei[e1];  d1 = (int)ei[E + e1]; }
    } else {
        const int* ei = reinterpret_cast<const int*>(ei_raw);
        s0 = ei[e0];  d0 = ei[E + e0];
        if (has2) { s1 = ei[e1];  d1 = ei[E + e1]; }
    }
    float w0 = __ldg(w + e0);
    float w1 = has2 ? __ldg(w + e1) : 0.f;

    float4 v0, v1 = make_float4(0.f, 0.f, 0.f, 0.f);
    float* dstE;
    if (layer == 0) {
        const float* p0 = (s0 < NUSERS) ? (users + (size_t)s0 * DIM)
                                        : (items + (size_t)(s0 - NUSERS) * DIM);
        v0 = *reinterpret_cast<const float4*>(p0 + c);
        if (has2) {
            const float* p1 = (s1 < NUSERS) ? (users + (size_t)s1 * DIM)
                                            : (items + (size_t)(s1 - NUSERS) * DIM);
            v1 = *reinterpret_cast<const float4*>(p1 + c);
        }
        dstE = g_B;
    } else {
        v0 = *reinterpret_cast<const float4*>(g_B + (size_t)s0 * DIM + c);
        if (has2)
            v1 = *reinterpret_cast<const float4*>(g_B + (size_t)s1 * DIM + c);
        v0.x = fmaxf(v0.x, 0.f); v0.y = fmaxf(v0.y, 0.f);
        v0.z = fmaxf(v0.z, 0.f); v0.w = fmaxf(v0.w, 0.f);
        v1.x = fmaxf(v1.x, 0.f); v1.y = fmaxf(v1.y, 0.f);
        v1.z = fmaxf(v1.z, 0.f); v1.w = fmaxf(v1.w, 0.f);
        dstE = g_A;
    }

    {
        float* p = dstE + (size_t)d0 * DIM + c;
        asm volatile("red.global.add.v4.f32 [%0], {%1,%2,%3,%4};"
                     :: "l"(p), "f"(v0.x * w0), "f"(v0.y * w0),
                        "f"(v0.z * w0), "f"(v0.w * w0) : "memory");
    }
    if (has2) {
        float* p = dstE + (size_t)d1 * DIM + c;
        asm volatile("red.global.add.v4.f32 [%0], {%1,%2,%3,%4};"
                     :: "l"(p), "f"(v1.x * w1), "f"(v1.y * w1),
                        "f"(v1.z * w1), "f"(v1.w * w1) : "memory");
    }
}

// ------- final: a = (orig + relu(B) + relu(A))/3; out = a@W^T + b ----------
// 64-row x 64-col tile per block; 4x4 register tile per thread;
// float4 LDS for both operands (a stored transposed).
__global__ void __launch_bounds__(256)
k_final(const float* __restrict__ W, const float* __restrict__ b,
        const float* __restrict__ users, const float* __restrict__ items,
        float* __restrict__ out)
{
    __shared__ float Wt[DIM][DIM + 4];   // Wt[k][j] = W[j][k]; stride 68
    __shared__ float aT[DIM][DIM + 4];   // aT[k][rowL]; stride 68
    __shared__ float sb[DIM];

    const int t = threadIdx.x;
    for (int idx = t; idx < DIM * DIM; idx += 256) {
        int j = idx >> 6, k = idx & 63;
        Wt[k][j] = W[idx];
    }
    if (t < DIM) sb[t] = b[t];

    const int base = blockIdx.x * 64;

    // ---- load phase: 4 threads per row, 16 cols each ----
    {
        const int rowL  = t >> 2;
        const int row   = base + rowL;
        const int cbase = (t & 3) * 16;
        if (row < NNODES) {
            const float* orig_row = (row < NUSERS)
                ? users + (size_t)row * DIM
                : items + (size_t)(row - NUSERS) * DIM;
            float* copy_dst = (row < NUSERS)
                ? out + (size_t)NUSERS * DIM + (size_t)row * DIM
                : out + (size_t)2 * NUSERS * DIM + (size_t)NITEMS * DIM
                      + (size_t)(row - NUSERS) * DIM;
#pragma unroll
            for (int g = 0; g < 4; g++) {
                const int col = cbase + 4 * g;
                float4 o  = *reinterpret_cast<const float4*>(orig_row + col);
                float4 va = *reinterpret_cast<const float4*>(
                                g_A + (size_t)row * DIM + col);
                float4 vb = *reinterpret_cast<const float4*>(
                                g_B + (size_t)row * DIM + col);
                aT[col + 0][rowL] =
                    (o.x + fmaxf(vb.x, 0.f) + fmaxf(va.x, 0.f)) * (1.f / 3.f);
                aT[col + 1][rowL] =
                    (o.y + fmaxf(vb.y, 0.f) + fmaxf(va.y, 0.f)) * (1.f / 3.f);
                aT[col + 2][rowL] =
                    (o.z + fmaxf(vb.z, 0.f) + fmaxf(va.z, 0.f)) * (1.f / 3.f);
                aT[col + 3][rowL] =
                    (o.w + fmaxf(vb.w, 0.f) + fmaxf(va.w, 0.f)) * (1.f / 3.f);
                *reinterpret_cast<float4*>(copy_dst + col) = o;  // passthrough
            }
        } else {
#pragma unroll
            for (int g = 0; g < 4; g++) {
                const int col = cbase + 4 * g;
                aT[col + 0][rowL] = 0.f;
                aT[col + 1][rowL] = 0.f;
                aT[col + 2][rowL] = 0.f;
                aT[col + 3][rowL] = 0.f;
            }
        }
    }
    __syncthreads();

    // ---- compute phase: thread (ri, ci) -> rows 4ri..+3, cols 4ci..+3 ----
    const int ri = t >> 4;
    const int ci = t & 15;
    float acc[4][4] = {};

#pragma unroll
    for (int k = 0; k < DIM; k++) {
        float4 av = *reinterpret_cast<const float4*>(&aT[k][4 * ri]);
        float4 wv = *reinterpret_cast<const float4*>(&Wt[k][4 * ci]);
        acc[0][0] = fmaf(av.x, wv.x, acc[0][0]);
        acc[0][1] = fmaf(av.x, wv.y, acc[0][1]);
        acc[0][2] = fmaf(av.x, wv.z, acc[0][2]);
        acc[0][3] = fmaf(av.x, wv.w, acc[0][3]);
        acc[1][0] = fmaf(av.y, wv.x, acc[1][0]);
        acc[1][1] = fmaf(av.y, wv.y, acc[1][1]);
        acc[1][2] = fmaf(av.y, wv.z, acc[1][2]);
        acc[1][3] = fmaf(av.y, wv.w, acc[1][3]);
        acc[2][0] = fmaf(av.z, wv.x, acc[2][0]);
        acc[2][1] = fmaf(av.z, wv.y, acc[2][1]);
        acc[2][2] = fmaf(av.z, wv.z, acc[2][2]);
        acc[2][3] = fmaf(av.z, wv.w, acc[2][3]);
        acc[3][0] = fmaf(av.w, wv.x, acc[3][0]);
        acc[3][1] = fmaf(av.w, wv.y, acc[3][1]);
        acc[3][2] = fmaf(av.w, wv.z, acc[3][2]);
        acc[3][3] = fmaf(av.w, wv.w, acc[3][3]);
    }

    const float4 bias = *reinterpret_cast<const float4*>(&sb[4 * ci]);
#pragma unroll
    for (int r = 0; r < 4; r++) {
        const int row = base + 4 * ri + r;
        if (row >= NNODES) break;
        float4 s;
        s.x = acc[r][0] + bias.x;
        s.y = acc[r][1] + bias.y;
        s.z = acc[r][2] + bias.z;
        s.w = acc[r][3] + bias.w;
        float* dst = (row < NUSERS)
            ? out + (size_t)row * DIM
            : out + (size_t)2 * NUSERS * DIM + (size_t)(row - NUSERS) * DIM;
        *reinterpret_cast<float4*>(dst + 4 * ci) = s;
    }
}

// ---------------------------------------------------------------------------
extern "C" void kernel_launch(void* const* d_in, const int* in_sizes, int n_in,
                              void* d_out, int out_size)
{
    const void*  ei    = d_in[0];
    const float* w     = (const float*)d_in[1];
    const float* users = (const float*)d_in[2];
    const float* items = (const float*)d_in[3];
    const float* W     = (const float*)d_in[4];
    const float* b     = (const float*)d_in[5];
    float* out = (float*)d_out;

    const int E  = in_sizes[1];       // edge_weight element count
    const int Eh = (E + 1) / 2;

    k_zero<<<2048, 256>>>((const long long*)ei);

    int sblocks = (Eh * 16 + 255) / 256;
    k_scatter<<<sblocks, 256>>>(ei, w, users, items, E, Eh, 0); // inputs -> B
    k_scatter<<<sblocks, 256>>>(ei, w, users, items, E, Eh, 1); // relu(B) -> A

    k_final<<<(NNODES + 63) / 64, 256>>>(W, b, users, items, out);
}